// round 13
// baseline (speedup 1.0000x reference)
#include <cuda_runtime.h>
#include <cuda_fp16.h>
#include <cstdint>

#define BATCH 16
#define SEQ   2048
#define DIN   4096
#define DOUT  4096
#define RANK  64
#define SCALING (1.0f/64.0f)

// ---------------- device scratch (no allocations allowed) -------------------
__device__ unsigned short g_Bh[(size_t)BATCH * RANK * DIN];   // B fp16 [b][r][k]
__device__ unsigned short g_Ah[(size_t)BATCH * DOUT * RANK];  // A fp16 [b][o][r]

// ---------------- helpers ----------------------------------------------------
__device__ __forceinline__ uint32_t smem_u32(const void* p) {
    uint32_t a;
    asm("{ .reg .u64 t; cvta.to.shared.u64 t, %1; cvt.u32.u64 %0, t; }"
        : "=r"(a) : "l"(p));
    return a;
}
#define SW128(o) ((uint32_t)(o) ^ ((((uint32_t)(o)) >> 3) & 0x70))

__device__ __forceinline__ uint32_t h2u(__half2 h) {
    return *reinterpret_cast<uint32_t*>(&h);
}

// cp.async (portable PTX, sm_80+)
#define CP_ASYNC16(dst, src) \
    asm volatile("cp.async.cg.shared.global [%0], [%1], 16;" :: "r"(dst), "l"(src))
#define CP_COMMIT() asm volatile("cp.async.commit_group;" ::: "memory")
#define CP_WAIT2()  asm volatile("cp.async.wait_group 2;" ::: "memory")

// ldmatrix x4 (portable PTX, sm_75+)
#define LDSM4(r0, r1, r2, r3, addr) \
    asm volatile("ldmatrix.sync.aligned.m8n8.x4.shared.b16 {%0,%1,%2,%3}, [%4];" \
        : "=r"(r0), "=r"(r1), "=r"(r2), "=r"(r3) : "r"(addr))

// mma.sync fp16, fp32 accumulate (portable PTX, sm_80+)
#define MMA(d, a, b0v, b1v) \
    asm volatile("mma.sync.aligned.m16n8k16.row.col.f32.f16.f16.f32 " \
        "{%0,%1,%2,%3}, {%4,%5,%6,%7}, {%8,%9}, {%0,%1,%2,%3};" \
        : "+f"((d)[0]), "+f"((d)[1]), "+f"((d)[2]), "+f"((d)[3]) \
        : "r"((a)[0]), "r"((a)[1]), "r"((a)[2]), "r"((a)[3]), "r"(b0v), "r"(b1v))

// ---------------------------------------------------------------------------
// adapter id resolution (int64 or int32 buffer; reads first 64 bytes only)
// ---------------------------------------------------------------------------
__device__ __forceinline__ int resolve_id(const int* raw, int b) {
    bool odd_zero = true;
    #pragma unroll
    for (int i = 1; i < 16; i += 2) odd_zero &= (raw[i] == 0);
    return odd_zero ? raw[2 * b] : raw[b];
}

// ---------------------------------------------------------------------------
// Convert requested A/B adapter slices to fp16.
// grid (128, BATCH, 2), block 256. z=0: B, z=1: A.
// ---------------------------------------------------------------------------
__global__ __launch_bounds__(256) void split_kernel(const float* __restrict__ Am,
                                                    const float* __restrict__ Bm,
                                                    const int* __restrict__ ids) {
    const int b = blockIdx.y;
    const int aid = resolve_id(ids, b);
    const int which = blockIdx.z;
    const size_t i8 = (size_t)blockIdx.x * 256 + threadIdx.x;
    const size_t PER = (size_t)RANK * DIN;
    const float* src = (which ? Am : Bm) + (size_t)aid * PER + i8 * 8;
    unsigned short* dh = (which ? g_Ah : g_Bh) + (size_t)b * PER + i8 * 8;
    float4 v0 = *(const float4*)src;
    float4 v1 = *(const float4*)(src + 4);
    *(uint4*)dh = make_uint4(
        h2u(__floats2half2_rn(v0.x, v0.y)), h2u(__floats2half2_rn(v0.z, v0.w)),
        h2u(__floats2half2_rn(v1.x, v1.y)), h2u(__floats2half2_rn(v1.z, v1.w)));
}

// ---------------------------------------------------------------------------
// Fused LoRA kernel. CTA = (128-n tile, batch). 8 warps, warp owns 16 n-rows.
// Stage 1: Y[16x64] = fp16(x) @ fp16(B)^T, K=4096.
//   x: DIRECT LDG.64 into registers (a-frag elements are thread-private),
//      ping-pong k32 prefetch — no smem, no barrier on the x path.
//   B: cp.async k64 tiles (8KB, SW128), 4 buffers, barrier per k64 (64 total).
// Stage 2: out = fp16(Y/64) @ fp16(A)^T, 32 o-tiles of 128, direct STG.
// smem (65536 B): stage1 4 B-bufs @0 (4*8192); stage2 4 A-bufs @0 (4*16384).
// B schedule: issueB(0);issueB(1); for j: { issueB(j+2); WAIT2; BARRIER;
// compute(j) } — issueB(j+2) writes buf (j+2)&3=(j-2)&3 whose readers finished
// before barrier(j-1).
// ---------------------------------------------------------------------------
#define BBUF_SZ (64 * 64 * 2)     // 8192: 64 r x 64 k fp16, SW128 128B rows
#define ABUF_SZ 16384             // 128 o x 64 r fp16
#define SMEM_TOTAL 65536

__global__ __launch_bounds__(256, 2) void fused_kernel(const float* __restrict__ x,
                                                       float* __restrict__ out) {
    extern __shared__ char smem[];
    const uint32_t sb = smem_u32(smem);
    const int tid = threadIdx.x;
    const int w = tid >> 5;
    const int lane = tid & 31;
    const int nt = blockIdx.x;
    const int b = blockIdx.y;

    const unsigned short* bhp = g_Bh + (size_t)b * RANK * DIN;
    const unsigned short* ahp = g_Ah + (size_t)b * DOUT * RANK;

    const int lrow = lane & 15;
    const int lkb = (lane >> 4) * 16;

    // ======================= STAGE 1 ========================================
    float acc[8][4];
    #pragma unroll
    for (int i = 0; i < 8; i++)
        #pragma unroll
        for (int j = 0; j < 4; j++) acc[i][j] = 0.f;

    // x row pointers for this thread's a-frag elements
    const int xr = w * 16 + (lane >> 2);
    const int xc = (lane & 3) * 2;
    const float* xt0 = x + ((size_t)b * SEQ + (size_t)nt * 128 + xr) * DIN + xc;
    const float* xt8 = xt0 + 8 * DIN;

    // ping-pong x registers: [buf][k16 within k32][4 elems]
    float2 xreg[2][8];
    auto loadx = [&](int c32, int buf) {
        if (c32 < 128) {
            const int k0 = c32 * 32;
            #pragma unroll
            for (int k16 = 0; k16 < 2; k16++) {
                const int cb = k0 + k16 * 16;
                xreg[buf][k16 * 4 + 0] = *(const float2*)(xt0 + cb);
                xreg[buf][k16 * 4 + 1] = *(const float2*)(xt8 + cb);
                xreg[buf][k16 * 4 + 2] = *(const float2*)(xt0 + cb + 8);
                xreg[buf][k16 * 4 + 3] = *(const float2*)(xt8 + cb + 8);
            }
        }
    };

    auto issueB = [&](int j) {
        if (j < 64) {
            const int buf = j & 3;
            const int k0 = j * 64;
            // B: 64 rows x 64 k fp16 = 512 x 16B, 2 per thread (SW128, 128B rows)
            #pragma unroll
            for (int t = 0; t < 2; t++) {
                int idx = tid + t * 256;
                int row = idx >> 3, f4 = idx & 7;
                CP_ASYNC16(sb + buf * BBUF_SZ + SW128(row * 128 + f4 * 16),
                           bhp + (size_t)row * DIN + k0 + f4 * 8);
            }
        }
        CP_COMMIT();
    };

    issueB(0);
    issueB(1);
    loadx(0, 0);
    for (int j = 0; j < 64; j++) {            // k64 chunks (B granularity)
        issueB(j + 2);
        CP_WAIT2();
        __syncthreads();
        const uint32_t bbase = sb + (j & 3) * BBUF_SZ;
        #pragma unroll
        for (int h = 0; h < 2; h++) {         // k32 halves
            const int c32 = 2 * j + h;
            loadx(c32 + 1, (c32 + 1) & 1);    // prefetch next k32
            const float2* xv = xreg[c32 & 1];
            #pragma unroll
            for (int k16 = 0; k16 < 2; k16++) {
                const int kc = h * 2 + k16;   // k16 index within the B k64 tile
                const float2* f = xv + k16 * 4;
                uint32_t a[4] = {
                    h2u(__floats2half2_rn(f[0].x, f[0].y)),
                    h2u(__floats2half2_rn(f[1].x, f[1].y)),
                    h2u(__floats2half2_rn(f[2].x, f[2].y)),
                    h2u(__floats2half2_rn(f[3].x, f[3].y))};
                #pragma unroll
                for (int nb = 0; nb < 4; nb++) {
                    uint32_t bh[4];
                    LDSM4(bh[0], bh[1], bh[2], bh[3],
                          bbase + SW128((nb * 16 + lrow) * 128 + kc * 32 + lkb));
                    MMA(acc[2 * nb],     a, bh[0], bh[2]);
                    MMA(acc[2 * nb + 1], a, bh[1], bh[3]);
                }
            }
        }
    }

    // D-frag -> stage2 a-frag, 1/64 LoRA scaling folded in.
    uint32_t bxh[4][4];
    #pragma unroll
    for (int kc = 0; kc < 4; kc++) {
        #pragma unroll
        for (int h = 0; h < 2; h++) {
            float* d = acc[2 * kc + h];
            bxh[kc][2 * h]     = h2u(__floats2half2_rn(d[0] * SCALING, d[1] * SCALING));
            bxh[kc][2 * h + 1] = h2u(__floats2half2_rn(d[2] * SCALING, d[3] * SCALING));
        }
    }
    __syncthreads();   // all stage1 smem reads done before stage2 overwrites

    // ======================= STAGE 2 ========================================
    const int r0 = lane >> 2;
    const int c0 = 2 * (lane & 3);
    const size_t orow0 = (size_t)b * SEQ + (size_t)nt * 128 + w * 16;

    auto issue2 = [&](int ot) {
        if (ot < 32) {
            const int buf = ot & 3;
            // A tile: 128 o x 64 r fp16 = 1024 x 16B, 4 per thread
            #pragma unroll
            for (int t = 0; t < 4; t++) {
                int idx = tid + t * 256;
                int row = idx >> 3, f4 = idx & 7;
                CP_ASYNC16(sb + buf * ABUF_SZ + SW128(row * 128 + f4 * 16),
                           ahp + (size_t)(ot * 128 + row) * RANK + f4 * 8);
            }
        }
        CP_COMMIT();
    };

    issue2(0);
    issue2(1);
    for (int ot = 0; ot < 32; ot++) {
        issue2(ot + 2);
        CP_WAIT2();
        __syncthreads();
        const uint32_t ab = sb + (ot & 3) * ABUF_SZ;
        #pragma unroll
        for (int nb = 0; nb < 8; nb++) {       // o-blocks of 16
            float d2[2][4];
            #pragma unroll
            for (int h = 0; h < 2; h++)
                #pragma unroll
                for (int j = 0; j < 4; j++) d2[h][j] = 0.f;
            #pragma unroll
            for (int kc = 0; kc < 4; kc++) {
                uint32_t Ah[4];
                LDSM4(Ah[0], Ah[1], Ah[2], Ah[3],
                      ab + SW128((nb * 16 + lrow) * 128 + kc * 32 + lkb));
                MMA(d2[0], bxh[kc], Ah[0], Ah[2]);
                MMA(d2[1], bxh[kc], Ah[1], Ah[3]);
            }
            // direct stores: quad-contiguous 32B segments (scaling pre-folded)
            float* o0 = out + (orow0 + r0) * DOUT + ot * 128 + nb * 16 + c0;
            float* o1 = out + (orow0 + r0 + 8) * DOUT + ot * 128 + nb * 16 + c0;
            *(float2*)o0       = make_float2(d2[0][0], d2[0][1]);
            *(float2*)o1       = make_float2(d2[0][2], d2[0][3]);
            *(float2*)(o0 + 8) = make_float2(d2[1][0], d2[1][1]);
            *(float2*)(o1 + 8) = make_float2(d2[1][2], d2[1][3]);
        }
    }
}

// ---------------------------------------------------------------------------
extern "C" void kernel_launch(void* const* d_in, const int* in_sizes, int n_in,
                              void* d_out, int out_size) {
    const float* x   = (const float*)d_in[0];
    const int*   ids = (const int*)  d_in[1];
    const float* A   = (const float*)d_in[2];
    const float* B   = (const float*)d_in[3];
    float* out = (float*)d_out;

    cudaFuncSetAttribute(fused_kernel, cudaFuncAttributeMaxDynamicSharedMemorySize,
                         SMEM_TOTAL);

    dim3 gS(128, BATCH, 2);
    split_kernel<<<gS, 256>>>(A, B, ids);

    dim3 gF(SEQ / 128, BATCH);
    fused_kernel<<<gF, 256, SMEM_TOTAL>>>(x, out);

    (void)in_sizes; (void)n_in; (void)out_size;
}

// round 14
// speedup vs baseline: 1.4500x; 1.4500x over previous
#include <cuda_runtime.h>
#include <cuda_fp16.h>
#include <cstdint>

#define BATCH 16
#define SEQ   2048
#define DIN   4096
#define DOUT  4096
#define RANK  64
#define SCALING (1.0f/64.0f)

// ---------------- device scratch (no allocations allowed) -------------------
__device__ unsigned short g_Bh[(size_t)BATCH * RANK * DIN];   // B fp16 [b][r][k]
__device__ unsigned short g_Ah[(size_t)BATCH * DOUT * RANK];  // A fp16 [b][o][r]

// ---------------- helpers ----------------------------------------------------
__device__ __forceinline__ uint32_t smem_u32(const void* p) {
    uint32_t a;
    asm("{ .reg .u64 t; cvta.to.shared.u64 t, %1; cvt.u32.u64 %0, t; }"
        : "=r"(a) : "l"(p));
    return a;
}
#define SW64(o)  ((uint32_t)(o) ^ ((((uint32_t)(o)) >> 3) & 0x30))
#define SW128(o) ((uint32_t)(o) ^ ((((uint32_t)(o)) >> 3) & 0x70))

__device__ __forceinline__ uint32_t h2u(__half2 h) {
    return *reinterpret_cast<uint32_t*>(&h);
}

// cp.async (portable PTX, sm_80+)
#define CP_ASYNC16(dst, src) \
    asm volatile("cp.async.cg.shared.global [%0], [%1], 16;" :: "r"(dst), "l"(src))
#define CP_COMMIT() asm volatile("cp.async.commit_group;" ::: "memory")
#define CP_WAIT1()  asm volatile("cp.async.wait_group 1;" ::: "memory")

// ldmatrix x4 (portable PTX, sm_75+)
#define LDSM4(r0, r1, r2, r3, addr) \
    asm volatile("ldmatrix.sync.aligned.m8n8.x4.shared.b16 {%0,%1,%2,%3}, [%4];" \
        : "=r"(r0), "=r"(r1), "=r"(r2), "=r"(r3) : "r"(addr))

// mma.sync fp16, fp32 accumulate (portable PTX, sm_80+)
#define MMA(d, a, b0v, b1v) \
    asm volatile("mma.sync.aligned.m16n8k16.row.col.f32.f16.f16.f32 " \
        "{%0,%1,%2,%3}, {%4,%5,%6,%7}, {%8,%9}, {%0,%1,%2,%3};" \
        : "+f"((d)[0]), "+f"((d)[1]), "+f"((d)[2]), "+f"((d)[3]) \
        : "r"((a)[0]), "r"((a)[1]), "r"((a)[2]), "r"((a)[3]), "r"(b0v), "r"(b1v))

// ---------------------------------------------------------------------------
// adapter id resolution (int64 or int32 buffer; reads first 64 bytes only)
// ---------------------------------------------------------------------------
__device__ __forceinline__ int resolve_id(const int* raw, int b) {
    bool odd_zero = true;
    #pragma unroll
    for (int i = 1; i < 16; i += 2) odd_zero &= (raw[i] == 0);
    return odd_zero ? raw[2 * b] : raw[b];
}

// ---------------------------------------------------------------------------
// Convert requested A/B adapter slices to fp16.
// grid (128, BATCH, 2), block 256. z=0: B, z=1: A.
// ---------------------------------------------------------------------------
__global__ __launch_bounds__(256) void split_kernel(const float* __restrict__ Am,
                                                    const float* __restrict__ Bm,
                                                    const int* __restrict__ ids) {
    const int b = blockIdx.y;
    const int aid = resolve_id(ids, b);
    const int which = blockIdx.z;
    const size_t i8 = (size_t)blockIdx.x * 256 + threadIdx.x;
    const size_t PER = (size_t)RANK * DIN;
    const float* src = (which ? Am : Bm) + (size_t)aid * PER + i8 * 8;
    unsigned short* dh = (which ? g_Ah : g_Bh) + (size_t)b * PER + i8 * 8;
    float4 v0 = *(const float4*)src;
    float4 v1 = *(const float4*)(src + 4);
    *(uint4*)dh = make_uint4(
        h2u(__floats2half2_rn(v0.x, v0.y)), h2u(__floats2half2_rn(v0.z, v0.w)),
        h2u(__floats2half2_rn(v1.x, v1.y)), h2u(__floats2half2_rn(v1.z, v1.w)));
}

// ---------------------------------------------------------------------------
// Fused LoRA kernel (single-term fp16, CK=32, 3-buffer cp.async, 3 CTA/SM).
// CTA = (128-n tile, batch). 8 warps, warp owns 16 n-rows.
// __launch_bounds__(256, 3): regs capped ~84 -> 24 resident warps/SM.
// Stage 1: Y[16x64] = fp16(x) @ fp16(B)^T  (K=4096 in 128 chunks of 32)
// Stage 2: out = fp16(Y/64) @ fp16(A)^T, 32 o-tiles of 128, direct STG.
// smem (73728 B = 228KB/3):
//   stage1: 3 x-bufs [128][40] fp32 @0 (3*20480), 3 B-bufs @61440 (3*4096)
//   stage2: 3 A-bufs @0 (3*16384)
// Schedule per iter (R8-proven, 3 buffers):
//   WAIT1; BARRIER; issue(c+2); compute(c)
// issue(c+2) writes buf (c+2)%3 == (c-1)%3, whose readers (compute(c-1))
// finished before this iteration's barrier -> race-free.
// ---------------------------------------------------------------------------
#define CK 32
#define NCH (DIN / CK)            // 128
#define XS 40                     // fp32 row stride in words (160B)
#define XBUF_SZ (128 * XS * 4)    // 20480
#define BBUF_SZ (64 * CK * 2)     // 4096
#define S_B 61440
#define ABUF_SZ 16384             // 128 o x 64 r fp16
#define SMEM_TOTAL 73728

__global__ __launch_bounds__(256, 3) void fused_kernel(const float* __restrict__ x,
                                                       float* __restrict__ out) {
    extern __shared__ char smem[];
    const uint32_t sb = smem_u32(smem);
    const int tid = threadIdx.x;
    const int w = tid >> 5;
    const int lane = tid & 31;
    const int nt = blockIdx.x;
    const int b = blockIdx.y;

    const float* xp = x + ((size_t)b * SEQ + (size_t)nt * 128) * DIN;
    const unsigned short* bhp = g_Bh + (size_t)b * RANK * DIN;
    const unsigned short* ahp = g_Ah + (size_t)b * DOUT * RANK;

    const int lrow = lane & 15;
    const int lkb = (lane >> 4) * 16;

    // ======================= STAGE 1 ========================================
    float acc[8][4];
    #pragma unroll
    for (int i = 0; i < 8; i++)
        #pragma unroll
        for (int j = 0; j < 4; j++) acc[i][j] = 0.f;

    auto issue1 = [&](int ch) {
        if (ch < NCH) {
            const int buf = ch % 3;
            const int k0 = ch * CK;
            // x: 128 rows x 32 fp32 = 1024 x 16B, 4 per thread
            #pragma unroll
            for (int t = 0; t < 4; t++) {
                int idx = tid + t * 256;
                int row = idx >> 3, f4 = idx & 7;
                CP_ASYNC16(sb + buf * XBUF_SZ + row * (XS * 4) + f4 * 16,
                           xp + (size_t)row * DIN + k0 + f4 * 4);
            }
            // B: 64 rows x 32 fp16 = 256 x 16B, 1 per thread (SW64, 64B rows)
            {
                int row = tid >> 2, f4 = tid & 3;
                CP_ASYNC16(sb + S_B + buf * BBUF_SZ + SW64(row * 64 + f4 * 16),
                           bhp + (size_t)row * DIN + k0 + f4 * 8);
            }
        }
        CP_COMMIT();
    };

    issue1(0);
    issue1(1);
    const int xr = w * 16 + (lane >> 2);       // a-frag row
    const int xc = (lane & 3) * 2;             // a-frag col base
    for (int c = 0; c < NCH; c++) {
        CP_WAIT1();
        __syncthreads();
        issue1(c + 2);
        const float* xb = (const float*)(smem + (c % 3) * XBUF_SZ);
        const uint32_t bbase = sb + S_B + (c % 3) * BBUF_SZ;
        #pragma unroll
        for (int kc = 0; kc < 2; kc++) {
            const int cb = kc * 16 + xc;
            float2 f0 = *(const float2*)(xb + xr * XS + cb);
            float2 f1 = *(const float2*)(xb + (xr + 8) * XS + cb);
            float2 f2 = *(const float2*)(xb + xr * XS + cb + 8);
            float2 f3 = *(const float2*)(xb + (xr + 8) * XS + cb + 8);
            uint32_t a[4] = {
                h2u(__floats2half2_rn(f0.x, f0.y)), h2u(__floats2half2_rn(f1.x, f1.y)),
                h2u(__floats2half2_rn(f2.x, f2.y)), h2u(__floats2half2_rn(f3.x, f3.y))};
            #pragma unroll
            for (int nb = 0; nb < 4; nb++) {
                uint32_t bh[4];
                LDSM4(bh[0], bh[1], bh[2], bh[3],
                      bbase + SW64((nb * 16 + lrow) * 64 + kc * 32 + lkb));
                MMA(acc[2 * nb],     a, bh[0], bh[2]);
                MMA(acc[2 * nb + 1], a, bh[1], bh[3]);
            }
        }
    }

    // D-frag -> stage2 a-frag, 1/64 LoRA scaling folded in.
    uint32_t bxh[4][4];
    #pragma unroll
    for (int kc = 0; kc < 4; kc++) {
        #pragma unroll
        for (int h = 0; h < 2; h++) {
            float* d = acc[2 * kc + h];
            bxh[kc][2 * h]     = h2u(__floats2half2_rn(d[0] * SCALING, d[1] * SCALING));
            bxh[kc][2 * h + 1] = h2u(__floats2half2_rn(d[2] * SCALING, d[3] * SCALING));
        }
    }
    __syncthreads();   // all stage1 smem reads done before stage2 overwrites

    // ======================= STAGE 2 ========================================
    const int r0 = lane >> 2;
    const int c0 = 2 * (lane & 3);
    const size_t orow0 = (size_t)b * SEQ + (size_t)nt * 128 + w * 16;

    auto issue2 = [&](int ot) {
        if (ot < 32) {
            const int buf = ot % 3;
            // A tile: 128 o x 64 r fp16 = 1024 x 16B, 4 per thread
            #pragma unroll
            for (int t = 0; t < 4; t++) {
                int idx = tid + t * 256;
                int row = idx >> 3, f4 = idx & 7;
                CP_ASYNC16(sb + buf * ABUF_SZ + SW128(row * 128 + f4 * 16),
                           ahp + (size_t)(ot * 128 + row) * RANK + f4 * 8);
            }
        }
        CP_COMMIT();
    };

    issue2(0);
    issue2(1);
    for (int ot = 0; ot < 32; ot++) {
        CP_WAIT1();
        __syncthreads();
        issue2(ot + 2);
        const uint32_t ab = sb + (ot % 3) * ABUF_SZ;
        #pragma unroll
        for (int nb = 0; nb < 8; nb++) {       // o-blocks of 16
            float d2[2][4];
            #pragma unroll
            for (int h = 0; h < 2; h++)
                #pragma unroll
                for (int j = 0; j < 4; j++) d2[h][j] = 0.f;
            #pragma unroll
            for (int kc = 0; kc < 4; kc++) {
                uint32_t Ah[4];
                LDSM4(Ah[0], Ah[1], Ah[2], Ah[3],
                      ab + SW128((nb * 16 + lrow) * 128 + kc * 32 + lkb));
                MMA(d2[0], bxh[kc], Ah[0], Ah[2]);
                MMA(d2[1], bxh[kc], Ah[1], Ah[3]);
            }
            // direct stores: quad-contiguous 32B segments (scaling pre-folded)
            float* o0 = out + (orow0 + r0) * DOUT + ot * 128 + nb * 16 + c0;
            float* o1 = out + (orow0 + r0 + 8) * DOUT + ot * 128 + nb * 16 + c0;
            *(float2*)o0       = make_float2(d2[0][0], d2[0][1]);
            *(float2*)o1       = make_float2(d2[0][2], d2[0][3]);
            *(float2*)(o0 + 8) = make_float2(d2[1][0], d2[1][1]);
            *(float2*)(o1 + 8) = make_float2(d2[1][2], d2[1][3]);
        }
    }
}

// ---------------------------------------------------------------------------
extern "C" void kernel_launch(void* const* d_in, const int* in_sizes, int n_in,
                              void* d_out, int out_size) {
    const float* x   = (const float*)d_in[0];
    const int*   ids = (const int*)  d_in[1];
    const float* A   = (const float*)d_in[2];
    const float* B   = (const float*)d_in[3];
    float* out = (float*)d_out;

    cudaFuncSetAttribute(fused_kernel, cudaFuncAttributeMaxDynamicSharedMemorySize,
                         SMEM_TOTAL);

    dim3 gS(128, BATCH, 2);
    split_kernel<<<gS, 256>>>(A, B, ids);

    dim3 gF(SEQ / 128, BATCH);
    fused_kernel<<<gF, 256, SMEM_TOTAL>>>(x, out);

    (void)in_sizes; (void)n_in; (void)out_size;
}

// round 15
// speedup vs baseline: 1.4999x; 1.0345x over previous
#include <cuda_runtime.h>
#include <cuda_fp16.h>
#include <cstdint>

#define BATCH 16
#define SEQ   2048
#define DIN   4096
#define DOUT  4096
#define RANK  64
#define SCALING (1.0f/64.0f)

// ---------------- device scratch (no allocations allowed) -------------------
__device__ unsigned short g_Bh[(size_t)BATCH * RANK * DIN];   // B fp16 [b][r][k]
__device__ unsigned short g_Ah[(size_t)BATCH * DOUT * RANK];  // A fp16 [b][o][r]

// ---------------- helpers ----------------------------------------------------
__device__ __forceinline__ uint32_t smem_u32(const void* p) {
    uint32_t a;
    asm("{ .reg .u64 t; cvta.to.shared.u64 t, %1; cvt.u32.u64 %0, t; }"
        : "=r"(a) : "l"(p));
    return a;
}
#define SW64(o)  ((uint32_t)(o) ^ ((((uint32_t)(o)) >> 3) & 0x30))
#define SW128(o) ((uint32_t)(o) ^ ((((uint32_t)(o)) >> 3) & 0x70))

__device__ __forceinline__ uint32_t h2u(__half2 h) {
    return *reinterpret_cast<uint32_t*>(&h);
}

// cp.async (portable PTX, sm_80+)
#define CP_ASYNC16(dst, src) \
    asm volatile("cp.async.cg.shared.global [%0], [%1], 16;" :: "r"(dst), "l"(src))
#define CP_COMMIT() asm volatile("cp.async.commit_group;" ::: "memory")
#define CP_WAIT2()  asm volatile("cp.async.wait_group 2;" ::: "memory")
#define CP_WAIT3()  asm volatile("cp.async.wait_group 3;" ::: "memory")

// ldmatrix x4 (portable PTX, sm_75+)
#define LDSM4(r0, r1, r2, r3, addr) \
    asm volatile("ldmatrix.sync.aligned.m8n8.x4.shared.b16 {%0,%1,%2,%3}, [%4];" \
        : "=r"(r0), "=r"(r1), "=r"(r2), "=r"(r3) : "r"(addr))

// mma.sync fp16, fp32 accumulate (portable PTX, sm_80+)
#define MMA(d, a, b0v, b1v) \
    asm volatile("mma.sync.aligned.m16n8k16.row.col.f32.f16.f16.f32 " \
        "{%0,%1,%2,%3}, {%4,%5,%6,%7}, {%8,%9}, {%0,%1,%2,%3};" \
        : "+f"((d)[0]), "+f"((d)[1]), "+f"((d)[2]), "+f"((d)[3]) \
        : "r"((a)[0]), "r"((a)[1]), "r"((a)[2]), "r"((a)[3]), "r"(b0v), "r"(b1v))

// ---------------------------------------------------------------------------
// adapter id resolution (int64 or int32 buffer; reads first 64 bytes only)
// ---------------------------------------------------------------------------
__device__ __forceinline__ int resolve_id(const int* raw, int b) {
    bool odd_zero = true;
    #pragma unroll
    for (int i = 1; i < 16; i += 2) odd_zero &= (raw[i] == 0);
    return odd_zero ? raw[2 * b] : raw[b];
}

// ---------------------------------------------------------------------------
// Convert requested A/B adapter slices to fp16.
// grid (128, BATCH, 2), block 256. z=0: B, z=1: A.
// ---------------------------------------------------------------------------
__global__ __launch_bounds__(256) void split_kernel(const float* __restrict__ Am,
                                                    const float* __restrict__ Bm,
                                                    const int* __restrict__ ids) {
    const int b = blockIdx.y;
    const int aid = resolve_id(ids, b);
    const int which = blockIdx.z;
    const size_t i8 = (size_t)blockIdx.x * 256 + threadIdx.x;
    const size_t PER = (size_t)RANK * DIN;
    const float* src = (which ? Am : Bm) + (size_t)aid * PER + i8 * 8;
    unsigned short* dh = (which ? g_Ah : g_Bh) + (size_t)b * PER + i8 * 8;
    float4 v0 = *(const float4*)src;
    float4 v1 = *(const float4*)(src + 4);
    *(uint4*)dh = make_uint4(
        h2u(__floats2half2_rn(v0.x, v0.y)), h2u(__floats2half2_rn(v0.z, v0.w)),
        h2u(__floats2half2_rn(v1.x, v1.y)), h2u(__floats2half2_rn(v1.z, v1.w)));
}

// ---------------------------------------------------------------------------
// Fused LoRA kernel (single-term fp16). CTA = (128-n tile, batch), 8 warps.
// Stage 1 (R12-proven): Y[16x64] = fp16(x) @ fp16(B)^T, K=4096 in 128 k32
//   chunks; 4 buffers, issue-2-ahead, wait_group 2.
// Stage 2: out = fp16(Y/64) @ fp16(A)^T, 32 o-tiles of 128, direct STG;
//   6 buffers, issue-4-ahead, wait_group 3 (deeper pipeline than R12).
// smem (98304 B):
//   stage1: 4 x-bufs [128][40] fp32 @0 (4*20480), 4 B-bufs @81920 (4*4096)
//   stage2: 6 A-bufs @0 (6*16384)
// Stage1 schedule: issue(0);issue(1); for c { issue(c+2); WAIT2; BAR;
//   compute(c) } — issue(c+2) writes buf (c-2)%4; its readers finished
//   before barrier(c-1), which all threads passed.
// Stage2 schedule: issue(0..3); for ot { issue(ot+4); WAIT3; BAR;
//   compute(ot) } — issue(ot+4) writes buf (ot+4)%6 = (ot-2)%6; its readers
//   (compute at ot-2) finished before barrier(ot-1) -> race-free.
// ---------------------------------------------------------------------------
#define CK 32
#define NCH (DIN / CK)            // 128
#define XS 40                     // fp32 row stride in words (160B, 2-phase LDS)
#define XBUF_SZ (128 * XS * 4)    // 20480
#define BBUF_SZ (64 * CK * 2)     // 4096
#define S_B 81920
#define ABUF_SZ 16384             // 128 o x 64 r fp16
#define SMEM_TOTAL 98304

__global__ __launch_bounds__(256, 2) void fused_kernel(const float* __restrict__ x,
                                                       float* __restrict__ out) {
    extern __shared__ char smem[];
    const uint32_t sb = smem_u32(smem);
    const int tid = threadIdx.x;
    const int w = tid >> 5;
    const int lane = tid & 31;
    const int nt = blockIdx.x;
    const int b = blockIdx.y;

    const float* xp = x + ((size_t)b * SEQ + (size_t)nt * 128) * DIN;
    const unsigned short* bhp = g_Bh + (size_t)b * RANK * DIN;
    const unsigned short* ahp = g_Ah + (size_t)b * DOUT * RANK;

    const int lrow = lane & 15;
    const int lkb = (lane >> 4) * 16;

    // ======================= STAGE 1 ========================================
    float acc[8][4];
    #pragma unroll
    for (int i = 0; i < 8; i++)
        #pragma unroll
        for (int j = 0; j < 4; j++) acc[i][j] = 0.f;

    auto issue1 = [&](int ch) {
        if (ch < NCH) {
            const int buf = ch & 3;
            const int k0 = ch * CK;
            // x: 128 rows x 32 fp32 = 1024 x 16B, 4 per thread
            #pragma unroll
            for (int t = 0; t < 4; t++) {
                int idx = tid + t * 256;
                int row = idx >> 3, f4 = idx & 7;
                CP_ASYNC16(sb + buf * XBUF_SZ + row * (XS * 4) + f4 * 16,
                           xp + (size_t)row * DIN + k0 + f4 * 4);
            }
            // B: 64 rows x 32 fp16 = 256 x 16B, 1 per thread (SW64, 64B rows)
            {
                int row = tid >> 2, f4 = tid & 3;
                CP_ASYNC16(sb + S_B + buf * BBUF_SZ + SW64(row * 64 + f4 * 16),
                           bhp + (size_t)row * DIN + k0 + f4 * 8);
            }
        }
        CP_COMMIT();
    };

    issue1(0);
    issue1(1);
    const int xr = w * 16 + (lane >> 2);       // a-frag row
    const int xc = (lane & 3) * 2;             // a-frag col base
    for (int c = 0; c < NCH; c++) {
        issue1(c + 2);
        CP_WAIT2();
        __syncthreads();
        const float* xb = (const float*)(smem + (c & 3) * XBUF_SZ);
        const uint32_t bbase = sb + S_B + (c & 3) * BBUF_SZ;
        #pragma unroll
        for (int kc = 0; kc < 2; kc++) {
            const int cb = kc * 16 + xc;
            float2 f0 = *(const float2*)(xb + xr * XS + cb);
            float2 f1 = *(const float2*)(xb + (xr + 8) * XS + cb);
            float2 f2 = *(const float2*)(xb + xr * XS + cb + 8);
            float2 f3 = *(const float2*)(xb + (xr + 8) * XS + cb + 8);
            uint32_t a[4] = {
                h2u(__floats2half2_rn(f0.x, f0.y)), h2u(__floats2half2_rn(f1.x, f1.y)),
                h2u(__floats2half2_rn(f2.x, f2.y)), h2u(__floats2half2_rn(f3.x, f3.y))};
            #pragma unroll
            for (int nb = 0; nb < 4; nb++) {
                uint32_t bh[4];
                LDSM4(bh[0], bh[1], bh[2], bh[3],
                      bbase + SW64((nb * 16 + lrow) * 64 + kc * 32 + lkb));
                MMA(acc[2 * nb],     a, bh[0], bh[2]);
                MMA(acc[2 * nb + 1], a, bh[1], bh[3]);
            }
        }
    }

    // D-frag -> stage2 a-frag, 1/64 LoRA scaling folded in.
    uint32_t bxh[4][4];
    #pragma unroll
    for (int kc = 0; kc < 4; kc++) {
        #pragma unroll
        for (int h = 0; h < 2; h++) {
            float* d = acc[2 * kc + h];
            bxh[kc][2 * h]     = h2u(__floats2half2_rn(d[0] * SCALING, d[1] * SCALING));
            bxh[kc][2 * h + 1] = h2u(__floats2half2_rn(d[2] * SCALING, d[3] * SCALING));
        }
    }
    __syncthreads();   // all stage1 smem reads done before stage2 overwrites

    // ======================= STAGE 2 ========================================
    const int r0 = lane >> 2;
    const int c0 = 2 * (lane & 3);
    const size_t orow0 = (size_t)b * SEQ + (size_t)nt * 128 + w * 16;

    auto issue2 = [&](int ot) {
        if (ot < 32) {
            const int buf = ot % 6;
            // A tile: 128 o x 64 r fp16 = 1024 x 16B, 4 per thread
            #pragma unroll
            for (int t = 0; t < 4; t++) {
                int idx = tid + t * 256;
                int row = idx >> 3, f4 = idx & 7;
                CP_ASYNC16(sb + buf * ABUF_SZ + SW128(row * 128 + f4 * 16),
                           ahp + (size_t)(ot * 128 + row) * RANK + f4 * 8);
            }
        }
        CP_COMMIT();
    };

    issue2(0);
    issue2(1);
    issue2(2);
    issue2(3);
    for (int ot = 0; ot < 32; ot++) {
        issue2(ot + 4);
        CP_WAIT3();
        __syncthreads();
        const uint32_t ab = sb + (ot % 6) * ABUF_SZ;
        #pragma unroll
        for (int nb = 0; nb < 8; nb++) {       // o-blocks of 16
            float d2[2][4];
            #pragma unroll
            for (int h = 0; h < 2; h++)
                #pragma unroll
                for (int j = 0; j < 4; j++) d2[h][j] = 0.f;
            #pragma unroll
            for (int kc = 0; kc < 4; kc++) {
                uint32_t Ah[4];
                LDSM4(Ah[0], Ah[1], Ah[2], Ah[3],
                      ab + SW128((nb * 16 + lrow) * 128 + kc * 32 + lkb));
                MMA(d2[0], bxh[kc], Ah[0], Ah[2]);
                MMA(d2[1], bxh[kc], Ah[1], Ah[3]);
            }
            // direct stores: quad-contiguous 32B segments (scaling pre-folded)
            float* o0 = out + (orow0 + r0) * DOUT + ot * 128 + nb * 16 + c0;
            float* o1 = out + (orow0 + r0 + 8) * DOUT + ot * 128 + nb * 16 + c0;
            *(float2*)o0       = make_float2(d2[0][0], d2[0][1]);
            *(float2*)o1       = make_float2(d2[0][2], d2[0][3]);
            *(float2*)(o0 + 8) = make_float2(d2[1][0], d2[1][1]);
            *(float2*)(o1 + 8) = make_float2(d2[1][2], d2[1][3]);
        }
    }
}

// ---------------------------------------------------------------------------
extern "C" void kernel_launch(void* const* d_in, const int* in_sizes, int n_in,
                              void* d_out, int out_size) {
    const float* x   = (const float*)d_in[0];
    const int*   ids = (const int*)  d_in[1];
    const float* A   = (const float*)d_in[2];
    const float* B   = (const float*)d_in[3];
    float* out = (float*)d_out;

    cudaFuncSetAttribute(fused_kernel, cudaFuncAttributeMaxDynamicSharedMemorySize,
                         SMEM_TOTAL);

    dim3 gS(128, BATCH, 2);
    split_kernel<<<gS, 256>>>(A, B, ids);

    dim3 gF(SEQ / 128, BATCH);
    fused_kernel<<<gF, 256, SMEM_TOTAL>>>(x, out);

    (void)in_sizes; (void)n_in; (void)out_size;
}

// round 16
// speedup vs baseline: 1.5932x; 1.0622x over previous
#include <cuda_runtime.h>
#include <cuda_fp16.h>
#include <cstdint>

#define BATCH 16
#define SEQ   2048
#define DIN   4096
#define DOUT  4096
#define RANK  64
#define SCALING (1.0f/64.0f)

// ---------------- device scratch (no allocations allowed) -------------------
__device__ unsigned short g_Bh[(size_t)BATCH * RANK * DIN];   // B fp16 [b][r][k]
__device__ unsigned short g_Ah[(size_t)BATCH * DOUT * RANK];  // A fp16 [b][o][r]

// ---------------- helpers ----------------------------------------------------
__device__ __forceinline__ uint32_t smem_u32(const void* p) {
    uint32_t a;
    asm("{ .reg .u64 t; cvta.to.shared.u64 t, %1; cvt.u32.u64 %0, t; }"
        : "=r"(a) : "l"(p));
    return a;
}
#define SW64(o)  ((uint32_t)(o) ^ ((((uint32_t)(o)) >> 3) & 0x30))
#define SW128(o) ((uint32_t)(o) ^ ((((uint32_t)(o)) >> 3) & 0x70))

__device__ __forceinline__ uint32_t h2u(__half2 h) {
    return *reinterpret_cast<uint32_t*>(&h);
}

// cp.async (portable PTX, sm_80+)
#define CP_ASYNC16(dst, src) \
    asm volatile("cp.async.cg.shared.global [%0], [%1], 16;" :: "r"(dst), "l"(src))
#define CP_COMMIT() asm volatile("cp.async.commit_group;" ::: "memory")
#define CP_WAIT2()  asm volatile("cp.async.wait_group 2;" ::: "memory")

// ldmatrix x4 (portable PTX, sm_75+)
#define LDSM4(r0, r1, r2, r3, addr) \
    asm volatile("ldmatrix.sync.aligned.m8n8.x4.shared.b16 {%0,%1,%2,%3}, [%4];" \
        : "=r"(r0), "=r"(r1), "=r"(r2), "=r"(r3) : "r"(addr))

// mma.sync fp16, fp32 accumulate (portable PTX, sm_80+)
#define MMA(d, a, b0v, b1v) \
    asm volatile("mma.sync.aligned.m16n8k16.row.col.f32.f16.f16.f32 " \
        "{%0,%1,%2,%3}, {%4,%5,%6,%7}, {%8,%9}, {%0,%1,%2,%3};" \
        : "+f"((d)[0]), "+f"((d)[1]), "+f"((d)[2]), "+f"((d)[3]) \
        : "r"((a)[0]), "r"((a)[1]), "r"((a)[2]), "r"((a)[3]), "r"(b0v), "r"(b1v))

// ---------------------------------------------------------------------------
// adapter id resolution (int64 or int32 buffer; reads first 64 bytes only)
// ---------------------------------------------------------------------------
__device__ __forceinline__ int resolve_id(const int* raw, int b) {
    bool odd_zero = true;
    #pragma unroll
    for (int i = 1; i < 16; i += 2) odd_zero &= (raw[i] == 0);
    return odd_zero ? raw[2 * b] : raw[b];
}

// ---------------------------------------------------------------------------
// Convert requested A/B adapter slices to fp16.
// grid (128, BATCH, 2), block 256. z=0: B, z=1: A.
// ---------------------------------------------------------------------------
__global__ __launch_bounds__(256) void split_kernel(const float* __restrict__ Am,
                                                    const float* __restrict__ Bm,
                                                    const int* __restrict__ ids) {
    const int b = blockIdx.y;
    const int aid = resolve_id(ids, b);
    const int which = blockIdx.z;
    const size_t i8 = (size_t)blockIdx.x * 256 + threadIdx.x;
    const size_t PER = (size_t)RANK * DIN;
    const float* src = (which ? Am : Bm) + (size_t)aid * PER + i8 * 8;
    unsigned short* dh = (which ? g_Ah : g_Bh) + (size_t)b * PER + i8 * 8;
    float4 v0 = *(const float4*)src;
    float4 v1 = *(const float4*)(src + 4);
    *(uint4*)dh = make_uint4(
        h2u(__floats2half2_rn(v0.x, v0.y)), h2u(__floats2half2_rn(v0.z, v0.w)),
        h2u(__floats2half2_rn(v1.x, v1.y)), h2u(__floats2half2_rn(v1.z, v1.w)));
}

// ---------------------------------------------------------------------------
// Fused LoRA kernel (single-term fp16). CTA = (128-n tile, batch), 8 warps.
// Stage 1 (R12-proven): Y[16x64]/warp = fp16(x) @ fp16(B)^T, 128 k32 chunks,
//   4 buffers, issue-2-ahead, wait_group 2.
// Y exchange: Y (scaled by 1/64) stored fp16 [128 n][64 r] in smem (dead
//   B-buf region), then re-read as a-frags via ldmatrix — lets stage 2 use
//   32-row warps.
// Stage 2 (reshaped): warp (g = w&3, h = w>>2) computes rows 32g..32g+31 x
//   o-half 64h..64h+63 of each 128-o tile -> each warp LDSMs only HALF the
//   A tile (8 KB vs 16 KB) => stage-2 smem read traffic halved.
// smem (98304 B):
//   stage1: 4 x-bufs [128][40] fp32 @0 (4*20480), 4 B-bufs @81920 (4*4096)
//   stage2: 4 A-bufs @0 (4*16384 = 65536), Y @81920 (16384)
// ---------------------------------------------------------------------------
#define CK 32
#define NCH (DIN / CK)            // 128
#define XS 40                     // fp32 row stride in words (160B)
#define XBUF_SZ (128 * XS * 4)    // 20480
#define BBUF_SZ (64 * CK * 2)     // 4096
#define S_B 81920
#define S_Y 81920                 // Y overlays dead B-buf region in stage 2
#define ABUF_SZ 16384             // 128 o x 64 r fp16
#define SMEM_TOTAL 98304

__global__ __launch_bounds__(256, 2) void fused_kernel(const float* __restrict__ x,
                                                       float* __restrict__ out) {
    extern __shared__ char smem[];
    const uint32_t sb = smem_u32(smem);
    const int tid = threadIdx.x;
    const int w = tid >> 5;
    const int lane = tid & 31;
    const int nt = blockIdx.x;
    const int b = blockIdx.y;

    const float* xp = x + ((size_t)b * SEQ + (size_t)nt * 128) * DIN;
    const unsigned short* bhp = g_Bh + (size_t)b * RANK * DIN;
    const unsigned short* ahp = g_Ah + (size_t)b * DOUT * RANK;

    const int lrow = lane & 15;
    const int lkb = (lane >> 4) * 16;

    // ======================= STAGE 1 ========================================
    float acc[8][4];
    #pragma unroll
    for (int i = 0; i < 8; i++)
        #pragma unroll
        for (int j = 0; j < 4; j++) acc[i][j] = 0.f;

    auto issue1 = [&](int ch) {
        if (ch < NCH) {
            const int buf = ch & 3;
            const int k0 = ch * CK;
            // x: 128 rows x 32 fp32 = 1024 x 16B, 4 per thread
            #pragma unroll
            for (int t = 0; t < 4; t++) {
                int idx = tid + t * 256;
                int row = idx >> 3, f4 = idx & 7;
                CP_ASYNC16(sb + buf * XBUF_SZ + row * (XS * 4) + f4 * 16,
                           xp + (size_t)row * DIN + k0 + f4 * 4);
            }
            // B: 64 rows x 32 fp16 = 256 x 16B, 1 per thread (SW64, 64B rows)
            {
                int row = tid >> 2, f4 = tid & 3;
                CP_ASYNC16(sb + S_B + buf * BBUF_SZ + SW64(row * 64 + f4 * 16),
                           bhp + (size_t)row * DIN + k0 + f4 * 8);
            }
        }
        CP_COMMIT();
    };

    issue1(0);
    issue1(1);
    const int xr = w * 16 + (lane >> 2);       // a-frag row
    const int xc = (lane & 3) * 2;             // a-frag col base
    for (int c = 0; c < NCH; c++) {
        issue1(c + 2);
        CP_WAIT2();
        __syncthreads();
        const float* xb = (const float*)(smem + (c & 3) * XBUF_SZ);
        const uint32_t bbase = sb + S_B + (c & 3) * BBUF_SZ;
        #pragma unroll
        for (int kc = 0; kc < 2; kc++) {
            const int cb = kc * 16 + xc;
            float2 f0 = *(const float2*)(xb + xr * XS + cb);
            float2 f1 = *(const float2*)(xb + (xr + 8) * XS + cb);
            float2 f2 = *(const float2*)(xb + xr * XS + cb + 8);
            float2 f3 = *(const float2*)(xb + (xr + 8) * XS + cb + 8);
            uint32_t a[4] = {
                h2u(__floats2half2_rn(f0.x, f0.y)), h2u(__floats2half2_rn(f1.x, f1.y)),
                h2u(__floats2half2_rn(f2.x, f2.y)), h2u(__floats2half2_rn(f3.x, f3.y))};
            #pragma unroll
            for (int nb = 0; nb < 4; nb++) {
                uint32_t bh[4];
                LDSM4(bh[0], bh[1], bh[2], bh[3],
                      bbase + SW64((nb * 16 + lrow) * 64 + kc * 32 + lkb));
                MMA(acc[2 * nb],     a, bh[0], bh[2]);
                MMA(acc[2 * nb + 1], a, bh[1], bh[3]);
            }
        }
    }

    // ---- Y exchange: store scaled fp16 Y to smem [128 n][64 r], SW128 -----
    // D-frag element map (validated in R9 round-trip): acc[2nb+p] holds
    //   rows (r0, r0+8), r-cols (nb*16 + p*8 + c0, +1) for p in {0,1}.
    __syncthreads();           // all x/B buffer reads retired
    {
        const int r0 = lane >> 2;
        const int c0 = 2 * (lane & 3);
        const int nrow = w * 16 + r0;
        #pragma unroll
        for (int nb = 0; nb < 4; nb++) {
            #pragma unroll
            for (int p = 0; p < 2; p++) {
                float* d = acc[2 * nb + p];
                int rcol = nb * 16 + p * 8 + c0;
                *(uint32_t*)(smem + S_Y + SW128(nrow * 128 + rcol * 2)) =
                    h2u(__floats2half2_rn(d[0] * SCALING, d[1] * SCALING));
                *(uint32_t*)(smem + S_Y + SW128((nrow + 8) * 128 + rcol * 2)) =
                    h2u(__floats2half2_rn(d[2] * SCALING, d[3] * SCALING));
            }
        }
    }

    // ======================= STAGE 2 ========================================
    const int g = w & 3;          // row group: rows 32g .. 32g+31
    const int h = w >> 2;         // o-half: 64h .. 64h+63 within each tile

    auto issue2 = [&](int ot) {
        if (ot < 32) {
            const int buf = ot & 3;
            // A tile: 128 o x 64 r fp16 = 1024 x 16B, 4 per thread
            #pragma unroll
            for (int t = 0; t < 4; t++) {
                int idx = tid + t * 256;
                int row = idx >> 3, f4 = idx & 7;
                CP_ASYNC16(sb + buf * ABUF_SZ + SW128(row * 128 + f4 * 16),
                           ahp + (size_t)(ot * 128 + row) * RANK + f4 * 8);
            }
        }
        CP_COMMIT();
    };

    issue2(0);                 // A-bufs @0 overlay x-bufs (dead after barrier)
    issue2(1);
    __syncthreads();           // Y visible to all warps

    // Load this warp's Y a-frags: 32 rows x 64 r, canonical ldmatrix.x4
    uint32_t bxh[2][4][4];     // [row-half s][kc][frag]
    #pragma unroll
    for (int s = 0; s < 2; s++)
        #pragma unroll
        for (int kc = 0; kc < 4; kc++)
            LDSM4(bxh[s][kc][0], bxh[s][kc][1], bxh[s][kc][2], bxh[s][kc][3],
                  sb + S_Y + SW128((g * 32 + s * 16 + lrow) * 128 + kc * 32 + lkb));

    const int r0 = lane >> 2;
    const int c0 = 2 * (lane & 3);
    const size_t orow0 = (size_t)b * SEQ + (size_t)nt * 128 + g * 32;

    for (int ot = 0; ot < 32; ot++) {
        issue2(ot + 2);
        CP_WAIT2();
        __syncthreads();
        const uint32_t ab = sb + (ot & 3) * ABUF_SZ;
        #pragma unroll
        for (int nb = 0; nb < 4; nb++) {       // 16-o blocks in this o-half
            const int ob = h * 64 + nb * 16;   // o offset within tile
            uint32_t Ah[4];
            float d2[2][2][4];
            #pragma unroll
            for (int s = 0; s < 2; s++)
                #pragma unroll
                for (int q = 0; q < 2; q++)
                    #pragma unroll
                    for (int j = 0; j < 4; j++) d2[s][q][j] = 0.f;
            #pragma unroll
            for (int kc = 0; kc < 4; kc++) {
                LDSM4(Ah[0], Ah[1], Ah[2], Ah[3],
                      ab + SW128((ob + lrow) * 128 + kc * 32 + lkb));
                #pragma unroll
                for (int s = 0; s < 2; s++) {
                    MMA(d2[s][0], bxh[s][kc], Ah[0], Ah[2]);
                    MMA(d2[s][1], bxh[s][kc], Ah[1], Ah[3]);
                }
            }
            // direct stores: quad-contiguous 32B segments (scaling pre-folded)
            #pragma unroll
            for (int s = 0; s < 2; s++) {
                float* o0 = out + (orow0 + s * 16 + r0) * DOUT
                          + ot * 128 + ob + c0;
                float* o1 = o0 + 8 * DOUT;
                *(float2*)o0       = make_float2(d2[s][0][0], d2[s][0][1]);
                *(float2*)o1       = make_float2(d2[s][0][2], d2[s][0][3]);
                *(float2*)(o0 + 8) = make_float2(d2[s][1][0], d2[s][1][1]);
                *(float2*)(o1 + 8) = make_float2(d2[s][1][2], d2[s][1][3]);
            }
        }
    }
}

// ---------------------------------------------------------------------------
extern "C" void kernel_launch(void* const* d_in, const int* in_sizes, int n_in,
                              void* d_out, int out_size) {
    const float* x   = (const float*)d_in[0];
    const int*   ids = (const int*)  d_in[1];
    const float* A   = (const float*)d_in[2];
    const float* B   = (const float*)d_in[3];
    float* out = (float*)d_out;

    cudaFuncSetAttribute(fused_kernel, cudaFuncAttributeMaxDynamicSharedMemorySize,
                         SMEM_TOTAL);

    dim3 gS(128, BATCH, 2);
    split_kernel<<<gS, 256>>>(A, B, ids);

    dim3 gF(SEQ / 128, BATCH);
    fused_kernel<<<gF, 256, SMEM_TOTAL>>>(x, out);

    (void)in_sizes; (void)n_in; (void)out_size;
}